// round 10
// baseline (speedup 1.0000x reference)
#include <cuda_runtime.h>
#include <math.h>

// ---------------------------------------------------------------------------
// DOSAConLoss — single-launch, 8-block, dedicated-pair-warp version.
//
// loss_loc factorizes (reference broadcasts (N,1)/(N,) -> (N,N) mean):
//   loss_loc = (Sum_i dw_i*hw_i*(1-ciou_i)^2.5) * (Sum_j 1/(area_j+1e-7)) / N^2
//
// 8 blocks x 928 threads (29 warps):
//   warps 0-15 : loc, TWO boxes per thread (i = blk*512+tid, i+4096)
//   warps 16-28: pair, one pair per warp (p = (w-16)*8 + blk, 104 >= 100)
//
// Halves vs R9: RED arrivals on A/B (512->256), completion bumps (16->8),
// block-finish spread. Accumulators {A,B,C,done} in ONE 16B sector; the
// acq_rel bump's acquire covers all release bumps, so the last block reads
// A,B,C with a single plain v4 load from the just-touched sector.
// ---------------------------------------------------------------------------

#define EPSF        1e-7f
#define ALPHA_C     1.2f
#define TAU_C       0.3f
#define DELTA_C     1.0f
#define FOUR_PI2    0.40528473456935108577f   // 4/pi^2

#define TPB         928          // 29 warps: 16 loc + 13 pair
#define LOC_THREADS 512
#define PAIR_WARP0  16
#define N_PAIR_WARPS 13

struct __align__(16) Acc {
    float accA;            // Σ dw*hw*(1-ciou)^2.5
    float accB;            // Σ 1/(area+1e-7)
    float accC;            // Σ masked pair loss
    unsigned int done;     // block completion counter
};
__device__ Acc g_acc = {0.0f, 0.0f, 0.0f, 0u};

__device__ __forceinline__ unsigned int atomic_inc_acq_rel(unsigned int* p) {
    unsigned int prev;
    asm volatile("atom.acq_rel.gpu.add.u32 %0, [%1], 1;"
                 : "=r"(prev) : "l"(p) : "memory");
    return prev;
}

__device__ __forceinline__ float4 ld_v4(const Acc* p) {
    float4 v;
    asm volatile("ld.global.v4.f32 {%0,%1,%2,%3}, [%4];"
                 : "=f"(v.x), "=f"(v.y), "=f"(v.z), "=f"(v.w)
                 : "l"(p) : "memory");
    return v;
}

__device__ __forceinline__ void st_v4(Acc* p, float4 v) {
    asm volatile("st.global.v4.f32 [%0], {%1,%2,%3,%4};"
                 :: "l"(p), "f"(v.x), "f"(v.y), "f"(v.z), "f"(v.w)
                 : "memory");
}

// fast sqrt for strictly non-negative t (uses MUFU.RSQ)
__device__ __forceinline__ float fast_sqrt_nn(float t) {
    float tc = fmaxf(t, 1e-30f);
    return t * __frsqrt_rn(tc);
}

// CIoU-based loc contributions for one box pair (returns {accA, accB})
__device__ __forceinline__ float2 loc_term(float4 b1, float4 b2, float dv) {
    float w1 = b1.z, h1 = b1.w, w2 = b2.z, h2 = b2.w;
    float b1x1 = b1.x - w1 * 0.5f, b1x2 = b1.x + w1 * 0.5f;
    float b1y1 = b1.y - h1 * 0.5f, b1y2 = b1.y + h1 * 0.5f;
    float b2x1 = b2.x - w2 * 0.5f, b2x2 = b2.x + w2 * 0.5f;
    float b2y1 = b2.y - h2 * 0.5f, b2y2 = b2.y + h2 * 0.5f;

    float iw = fmaxf(fminf(b1x2, b2x2) - fmaxf(b1x1, b2x1), 0.0f);
    float ih = fmaxf(fminf(b1y2, b2y2) - fmaxf(b1y1, b2y1), 0.0f);
    float inter = iw * ih;
    float uni   = w1 * h1 + w2 * h2 - inter + EPSF;
    float iou   = __fdividef(inter, uni);

    float cw = fmaxf(b1x2, b2x2) - fminf(b1x1, b2x1);
    float ch = fmaxf(b1y2, b2y2) - fminf(b1y1, b2y1);
    float c2 = cw * cw + ch * ch + EPSF;

    float dx = b2x1 + b2x2 - b1x1 - b1x2;
    float dy = b2y1 + b2y2 - b1y1 - b1y2;
    float rho2 = (dx * dx + dy * dy) * 0.25f;

    // atan(w2/h2) - atan(w1/h1) = atan((w2*h1 - w1*h2)/(h1*h2 + w1*w2))
    float num = w2 * h1 - w1 * h2;
    float den = fmaf(h1, h2, w1 * w2);
    float dat = atanf(__fdividef(num, den));
    float v   = FOUR_PI2 * dat * dat;
    float alpha = __fdividef(v, v - iou + (1.0f + EPSF));
    float ciou = iou - (__fdividef(rho2, c2) + v * alpha);

    float t  = 1.0f - ciou;                   // >= 0
    float pw = t * t * fast_sqrt_nn(t);       // t^2.5
    float dw = fmaf(ALPHA_C, dv, 1.0f);
    float hw = __fdividef(1.0f, 1.0f + __expf(fmaf(5.0f, ciou, -2.5f)));
    return make_float2(dw * hw * pw, __fdividef(1.0f, fmaf(w2, h2, 1e-7f)));
}

__global__ __launch_bounds__(TPB)
void dosa_split8_kernel(const float4* __restrict__ pred,
                        const float4* __restrict__ tgt,
                        const float*  __restrict__ emb,
                        const float*  __restrict__ dens,
                        const int2*   __restrict__ idx,
                        float* __restrict__ out,
                        int N, int D, int P, int nblocks,
                        float invN2, float pairScale) {
    int lane = threadIdx.x & 31;
    int warp = threadIdx.x >> 5;
    int locSpan = nblocks * LOC_THREADS;          // 4096

    if (warp >= PAIR_WARP0) {
        // ================= dedicated pair warps =================
        int p = (warp - PAIR_WARP0) * nblocks + blockIdx.x;
        if (p < P) {
            int2 ij = idx[p];
            int pi = ij.x, pj = ij.y;

            const float4* ei = (const float4*)(emb + (size_t)pi * D);
            const float4* ej = (const float4*)(emb + (size_t)pj * D);
            float4 bi = pred[pi];
            float4 bj = pred[pj];

            int D4 = D >> 2;                      // 64
            float s = 0.0f;
            for (int c = lane; c < D4; c += 32) { // 2 iterations at D=256
                float4 u = ei[c];
                float4 v = ej[c];
                float d0 = u.x - v.x, d1 = u.y - v.y;
                float d2 = u.z - v.z, d3 = u.w - v.w;
                s = fmaf(d0, d0, s); s = fmaf(d1, d1, s);
                s = fmaf(d2, d2, s); s = fmaf(d3, d3, s);
            }
            #pragma unroll
            for (int off = 16; off > 0; off >>= 1)
                s += __shfl_down_sync(0xffffffffu, s, off);

            if (lane == 0) {
                float a_x1 = bi.x - bi.z * 0.5f, a_x2 = bi.x + bi.z * 0.5f;
                float a_y1 = bi.y - bi.w * 0.5f, a_y2 = bi.y + bi.w * 0.5f;
                float b_x1 = bj.x - bj.z * 0.5f, b_x2 = bj.x + bj.z * 0.5f;
                float b_y1 = bj.y - bj.w * 0.5f, b_y2 = bj.y + bj.w * 0.5f;
                float iw = fmaxf(fminf(a_x2, b_x2) - fmaxf(a_x1, b_x1), 0.0f);
                float ih = fmaxf(fminf(a_y2, b_y2) - fmaxf(a_y1, b_y1), 0.0f);
                float inter = iw * ih;
                float uni = bi.z * bi.w + bj.z * bj.w - inter + EPSF;
                float piou = __fdividef(inter, uni);
                if (piou > TAU_C) {
                    float d = fast_sqrt_nn(s);
                    float t = fmaxf(DELTA_C - d, 0.0f);
                    if (t > 0.0f) atomicAdd(&g_acc.accC, t * t);
                }
            }
        }
    } else {
        // ============ loc warps: TWO boxes per thread ============
        int i0 = blockIdx.x * LOC_THREADS + threadIdx.x;
        int i1 = i0 + locSpan;

        float accA = 0.0f, accB = 0.0f;
        // issue all loads first (MLP), then math
        bool v0 = (i0 < N), v1 = (i1 < N);
        float4 p0, t0, p1, t1;
        float d0 = 0.0f, d1 = 0.0f;
        if (v0) { p0 = pred[i0]; t0 = tgt[i0]; d0 = dens[i0]; }
        if (v1) { p1 = pred[i1]; t1 = tgt[i1]; d1 = dens[i1]; }
        if (v0) { float2 r = loc_term(p0, t0, d0); accA += r.x; accB += r.y; }
        if (v1) { float2 r = loc_term(p1, t1, d1); accA += r.x; accB += r.y; }

        #pragma unroll
        for (int off = 16; off > 0; off >>= 1) {
            accA += __shfl_down_sync(0xffffffffu, accA, off);
            accB += __shfl_down_sync(0xffffffffu, accB, off);
        }
        if (lane == 0) {
            atomicAdd(&g_acc.accA, accA);             // RED.ADD (no return)
            atomicAdd(&g_acc.accB, accB);
        }
    }

    // ---- block completion: hb edge from all warps, then ONE bump ----
    __syncthreads();
    if (threadIdx.x != 0) return;

    unsigned int prev = atomic_inc_acq_rel(&g_acc.done);
    if (prev != (unsigned int)(nblocks - 1)) return;

    // last block: one v4 load fetches A,B,C from the just-touched sector
    float4 abc = ld_v4(&g_acc);
    out[0] = abc.x * abc.y * invN2 + abc.z * pairScale;
    st_v4(&g_acc, make_float4(0.0f, 0.0f, 0.0f, 0.0f));  // reset for replay
}

extern "C" void kernel_launch(void* const* d_in, const int* in_sizes, int n_in,
                              void* d_out, int out_size) {
    const float4* pred = (const float4*)d_in[0];
    const float4* tgt  = (const float4*)d_in[1];
    const float*  emb  = (const float*)d_in[2];
    const float*  dens = (const float*)d_in[3];
    const int2*   idx  = (const int2*)d_in[4];
    float* out = (float*)d_out;

    int N = in_sizes[0] / 4;
    int D = in_sizes[2] / N;
    int P = in_sizes[4] / 2;

    // 2 boxes per loc thread
    int blocks = (N + 2 * LOC_THREADS - 1) / (2 * LOC_THREADS);   // 8
    int pairSlots = blocks * N_PAIR_WARPS;                        // 104
    if (pairSlots < P)
        blocks = (P + N_PAIR_WARPS - 1) / N_PAIR_WARPS;           // safety

    float invN2 = 1.0f / ((float)N * (float)N);
    float pairScale = 0.5f / ((float)P + 1e-7f);

    dosa_split8_kernel<<<blocks, TPB>>>(pred, tgt, emb, dens, idx, out,
                                        N, D, P, blocks, invN2, pairScale);
}

// round 11
// speedup vs baseline: 1.1531x; 1.1531x over previous
#include <cuda_runtime.h>
#include <math.h>

// ---------------------------------------------------------------------------
// DOSAConLoss — single-launch, 32-block wide-spread version.
//
// loss_loc factorizes (reference broadcasts (N,1)/(N,) -> (N,N) mean):
//   loss_loc = (Sum_i dw_i*hw_i*(1-ciou_i)^2.5) * (Sum_j 1/(area_j+1e-7)) / N^2
//
// 32 blocks x 384 threads (12 warps):
//   warps 0-7 : loc, one box per thread (256 boxes/block, 8192 total)
//   warps 8-11: pair, one pair per warp (p = (w-8)*32 + blk, 128 >= 100)
//
// R10 lesson: kernel is per-warp latency bound -> spread across MORE SMs
// with FEWER warps per block (R10 went 8x29 and regressed; this goes 32x12).
// Accumulators {A,B,C,done} in ONE 16B sector; acq_rel bump per block; last
// block reads A,B,C with a single plain v4 load from the just-touched sector.
// ---------------------------------------------------------------------------

#define EPSF        1e-7f
#define ALPHA_C     1.2f
#define TAU_C       0.3f
#define DELTA_C     1.0f
#define FOUR_PI2    0.40528473456935108577f   // 4/pi^2

#define TPB          384          // 12 warps: 8 loc + 4 pair
#define LOC_THREADS  256
#define PAIR_WARP0   8
#define N_PAIR_WARPS 4

struct __align__(16) Acc {
    float accA;            // Σ dw*hw*(1-ciou)^2.5
    float accB;            // Σ 1/(area+1e-7)
    float accC;            // Σ masked pair loss
    unsigned int done;     // block completion counter
};
__device__ Acc g_acc = {0.0f, 0.0f, 0.0f, 0u};

__device__ __forceinline__ unsigned int atomic_inc_acq_rel(unsigned int* p) {
    unsigned int prev;
    asm volatile("atom.acq_rel.gpu.add.u32 %0, [%1], 1;"
                 : "=r"(prev) : "l"(p) : "memory");
    return prev;
}

__device__ __forceinline__ float4 ld_v4(const Acc* p) {
    float4 v;
    asm volatile("ld.global.v4.f32 {%0,%1,%2,%3}, [%4];"
                 : "=f"(v.x), "=f"(v.y), "=f"(v.z), "=f"(v.w)
                 : "l"(p) : "memory");
    return v;
}

__device__ __forceinline__ void st_v4(Acc* p, float4 v) {
    asm volatile("st.global.v4.f32 [%0], {%1,%2,%3,%4};"
                 :: "l"(p), "f"(v.x), "f"(v.y), "f"(v.z), "f"(v.w)
                 : "memory");
}

// fast sqrt for strictly non-negative t (uses MUFU.RSQ)
__device__ __forceinline__ float fast_sqrt_nn(float t) {
    float tc = fmaxf(t, 1e-30f);
    return t * __frsqrt_rn(tc);
}

__global__ __launch_bounds__(TPB)
void dosa_wide_kernel(const float4* __restrict__ pred,
                      const float4* __restrict__ tgt,
                      const float*  __restrict__ emb,
                      const float*  __restrict__ dens,
                      const int2*   __restrict__ idx,
                      float* __restrict__ out,
                      int N, int D, int P, int nblocks,
                      float invN2, float pairScale) {
    int lane = threadIdx.x & 31;
    int warp = threadIdx.x >> 5;

    if (warp >= PAIR_WARP0) {
        // ================= dedicated pair warps =================
        // Chain starts immediately: idx -> pred/emb gather -> reduce.
        int p = (warp - PAIR_WARP0) * nblocks + blockIdx.x;
        if (p < P) {
            int2 ij = idx[p];
            int pi = ij.x, pj = ij.y;

            const float4* ei = (const float4*)(emb + (size_t)pi * D);
            const float4* ej = (const float4*)(emb + (size_t)pj * D);
            float4 bi = pred[pi];
            float4 bj = pred[pj];

            int D4 = D >> 2;                      // 64
            float s = 0.0f;
            for (int c = lane; c < D4; c += 32) { // 2 iterations at D=256
                float4 u = ei[c];
                float4 v = ej[c];
                float d0 = u.x - v.x, d1 = u.y - v.y;
                float d2 = u.z - v.z, d3 = u.w - v.w;
                s = fmaf(d0, d0, s); s = fmaf(d1, d1, s);
                s = fmaf(d2, d2, s); s = fmaf(d3, d3, s);
            }
            #pragma unroll
            for (int off = 16; off > 0; off >>= 1)
                s += __shfl_down_sync(0xffffffffu, s, off);

            if (lane == 0) {
                float a_x1 = bi.x - bi.z * 0.5f, a_x2 = bi.x + bi.z * 0.5f;
                float a_y1 = bi.y - bi.w * 0.5f, a_y2 = bi.y + bi.w * 0.5f;
                float b_x1 = bj.x - bj.z * 0.5f, b_x2 = bj.x + bj.z * 0.5f;
                float b_y1 = bj.y - bj.w * 0.5f, b_y2 = bj.y + bj.w * 0.5f;
                float iw = fmaxf(fminf(a_x2, b_x2) - fmaxf(a_x1, b_x1), 0.0f);
                float ih = fmaxf(fminf(a_y2, b_y2) - fmaxf(a_y1, b_y1), 0.0f);
                float inter = iw * ih;
                float uni = bi.z * bi.w + bj.z * bj.w - inter + EPSF;
                float piou = __fdividef(inter, uni);
                if (piou > TAU_C) {
                    float d = fast_sqrt_nn(s);
                    float t = fmaxf(DELTA_C - d, 0.0f);
                    if (t > 0.0f) atomicAdd(&g_acc.accC, t * t);
                }
            }
        }
    } else {
        // ================= loc warps: one box per thread =================
        float accA = 0.0f, accB = 0.0f;
        int i = blockIdx.x * LOC_THREADS + threadIdx.x;
        if (i < N) {
            float4 b1 = pred[i];
            float4 b2 = tgt[i];
            float dv  = dens[i];

            float w1 = b1.z, h1 = b1.w, w2 = b2.z, h2 = b2.w;
            float b1x1 = b1.x - w1 * 0.5f, b1x2 = b1.x + w1 * 0.5f;
            float b1y1 = b1.y - h1 * 0.5f, b1y2 = b1.y + h1 * 0.5f;
            float b2x1 = b2.x - w2 * 0.5f, b2x2 = b2.x + w2 * 0.5f;
            float b2y1 = b2.y - h2 * 0.5f, b2y2 = b2.y + h2 * 0.5f;

            float iw = fmaxf(fminf(b1x2, b2x2) - fmaxf(b1x1, b2x1), 0.0f);
            float ih = fmaxf(fminf(b1y2, b2y2) - fmaxf(b1y1, b2y1), 0.0f);
            float inter = iw * ih;
            float uni   = w1 * h1 + w2 * h2 - inter + EPSF;
            float iou   = __fdividef(inter, uni);

            float cw = fmaxf(b1x2, b2x2) - fminf(b1x1, b2x1);
            float ch = fmaxf(b1y2, b2y2) - fminf(b1y1, b2y1);
            float c2 = cw * cw + ch * ch + EPSF;

            float dx = b2x1 + b2x2 - b1x1 - b1x2;
            float dy = b2y1 + b2y2 - b1y1 - b1y2;
            float rho2 = (dx * dx + dy * dy) * 0.25f;

            // atan(w2/h2) - atan(w1/h1) = atan((w2*h1 - w1*h2)/(h1*h2 + w1*w2))
            float num = w2 * h1 - w1 * h2;
            float den = fmaf(h1, h2, w1 * w2);
            float dat = atanf(__fdividef(num, den));
            float v   = FOUR_PI2 * dat * dat;
            float alpha = __fdividef(v, v - iou + (1.0f + EPSF));
            float ciou = iou - (__fdividef(rho2, c2) + v * alpha);

            float t  = 1.0f - ciou;                   // >= 0
            float pw = t * t * fast_sqrt_nn(t);       // t^2.5
            float dw = fmaf(ALPHA_C, dv, 1.0f);
            float hw = __fdividef(1.0f, 1.0f + __expf(fmaf(5.0f, ciou, -2.5f)));
            accA = dw * hw * pw;
            accB = __fdividef(1.0f, fmaf(w2, h2, 1e-7f));
        }
        #pragma unroll
        for (int off = 16; off > 0; off >>= 1) {
            accA += __shfl_down_sync(0xffffffffu, accA, off);
            accB += __shfl_down_sync(0xffffffffu, accB, off);
        }
        if (lane == 0) {
            atomicAdd(&g_acc.accA, accA);             // RED.ADD (no return)
            atomicAdd(&g_acc.accB, accB);
        }
    }

    // ---- block completion: hb edge from all warps, then ONE bump ----
    __syncthreads();
    if (threadIdx.x != 0) return;

    unsigned int prev = atomic_inc_acq_rel(&g_acc.done);
    if (prev != (unsigned int)(nblocks - 1)) return;

    // last block: one v4 load fetches A,B,C from the just-touched sector
    float4 abc = ld_v4(&g_acc);
    out[0] = abc.x * abc.y * invN2 + abc.z * pairScale;
    st_v4(&g_acc, make_float4(0.0f, 0.0f, 0.0f, 0.0f));  // reset for replay
}

extern "C" void kernel_launch(void* const* d_in, const int* in_sizes, int n_in,
                              void* d_out, int out_size) {
    const float4* pred = (const float4*)d_in[0];
    const float4* tgt  = (const float4*)d_in[1];
    const float*  emb  = (const float*)d_in[2];
    const float*  dens = (const float*)d_in[3];
    const int2*   idx  = (const int2*)d_in[4];
    float* out = (float*)d_out;

    int N = in_sizes[0] / 4;
    int D = in_sizes[2] / N;
    int P = in_sizes[4] / 2;

    int blocks = (N + LOC_THREADS - 1) / LOC_THREADS;     // 32
    int pairSlots = blocks * N_PAIR_WARPS;                // 128
    if (pairSlots < P)
        blocks = (P + N_PAIR_WARPS - 1) / N_PAIR_WARPS;   // safety (not hit)

    float invN2 = 1.0f / ((float)N * (float)N);
    float pairScale = 0.5f / ((float)P + 1e-7f);

    dosa_wide_kernel<<<blocks, TPB>>>(pred, tgt, emb, dens, idx, out,
                                      N, D, P, blocks, invN2, pairScale);
}

// round 12
// speedup vs baseline: 1.1587x; 1.0048x over previous
#include <cuda_runtime.h>
#include <math.h>

// ---------------------------------------------------------------------------
// DOSAConLoss — single-launch, 16-block dedicated-pair-warp version (best
// known R9 config) + fused two-lane RED for the loc accumulators.
//
// loss_loc factorizes (reference broadcasts (N,1)/(N,) -> (N,N) mean):
//   loss_loc = (Sum_i dw_i*hw_i*(1-ciou_i)^2.5) * (Sum_j 1/(area_j+1e-7)) / N^2
//
// 16 blocks x 736 threads (23 warps):
//   warps 0-15 : loc, one box per thread (512 boxes/block, 8192 total)
//   warps 16-22: pair, one pair per warp (p = (w-16)*16 + blk, 112 >= 100)
//     (high wid -> arbiter priority; pair chain = longest dependent path)
//
// Accumulators {A,B,C,done} in ONE 16B sector. Loc warps: shuffle reduce ->
// ONE RED instruction with lanes 0,1 targeting accA,accB (spread-address).
// __syncthreads + ONE acq_rel bump per block; last block reads A,B,C with a
// single plain v4 load from the just-touched sector, stores, resets.
// ---------------------------------------------------------------------------

#define EPSF        1e-7f
#define ALPHA_C     1.2f
#define TAU_C       0.3f
#define DELTA_C     1.0f
#define FOUR_PI2    0.40528473456935108577f   // 4/pi^2

#define TPB         736          // 23 warps: 16 loc + 7 pair
#define LOC_THREADS 512
#define PAIR_WARP0  16

struct __align__(16) Acc {
    float accA;            // Σ dw*hw*(1-ciou)^2.5
    float accB;            // Σ 1/(area+1e-7)
    float accC;            // Σ masked pair loss
    unsigned int done;     // block completion counter
};
__device__ Acc g_acc = {0.0f, 0.0f, 0.0f, 0u};

__device__ __forceinline__ unsigned int atomic_inc_acq_rel(unsigned int* p) {
    unsigned int prev;
    asm volatile("atom.acq_rel.gpu.add.u32 %0, [%1], 1;"
                 : "=r"(prev) : "l"(p) : "memory");
    return prev;
}

__device__ __forceinline__ float4 ld_v4(const Acc* p) {
    float4 v;
    asm volatile("ld.global.v4.f32 {%0,%1,%2,%3}, [%4];"
                 : "=f"(v.x), "=f"(v.y), "=f"(v.z), "=f"(v.w)
                 : "l"(p) : "memory");
    return v;
}

__device__ __forceinline__ void st_v4(Acc* p, float4 v) {
    asm volatile("st.global.v4.f32 [%0], {%1,%2,%3,%4};"
                 :: "l"(p), "f"(v.x), "f"(v.y), "f"(v.z), "f"(v.w)
                 : "memory");
}

// fast sqrt for strictly non-negative t (uses MUFU.RSQ)
__device__ __forceinline__ float fast_sqrt_nn(float t) {
    float tc = fmaxf(t, 1e-30f);
    return t * __frsqrt_rn(tc);
}

__global__ __launch_bounds__(TPB)
void dosa_split_kernel(const float4* __restrict__ pred,
                       const float4* __restrict__ tgt,
                       const float*  __restrict__ emb,
                       const float*  __restrict__ dens,
                       const int2*   __restrict__ idx,
                       float* __restrict__ out,
                       int N, int D, int P, int nblocks,
                       float invN2, float pairScale) {
    int lane = threadIdx.x & 31;
    int warp = threadIdx.x >> 5;

    if (warp >= PAIR_WARP0) {
        // ================= dedicated pair warps =================
        // Chain starts immediately: idx -> pred/emb gather -> reduce.
        int p = (warp - PAIR_WARP0) * nblocks + blockIdx.x;
        if (p < P) {
            int2 ij = idx[p];
            int pi = ij.x, pj = ij.y;

            const float4* ei = (const float4*)(emb + (size_t)pi * D);
            const float4* ej = (const float4*)(emb + (size_t)pj * D);
            float4 bi = pred[pi];
            float4 bj = pred[pj];

            int D4 = D >> 2;                      // 64
            float s = 0.0f;
            for (int c = lane; c < D4; c += 32) { // 2 iterations at D=256
                float4 u = ei[c];
                float4 v = ej[c];
                float d0 = u.x - v.x, d1 = u.y - v.y;
                float d2 = u.z - v.z, d3 = u.w - v.w;
                s = fmaf(d0, d0, s); s = fmaf(d1, d1, s);
                s = fmaf(d2, d2, s); s = fmaf(d3, d3, s);
            }
            #pragma unroll
            for (int off = 16; off > 0; off >>= 1)
                s += __shfl_down_sync(0xffffffffu, s, off);

            if (lane == 0) {
                float a_x1 = bi.x - bi.z * 0.5f, a_x2 = bi.x + bi.z * 0.5f;
                float a_y1 = bi.y - bi.w * 0.5f, a_y2 = bi.y + bi.w * 0.5f;
                float b_x1 = bj.x - bj.z * 0.5f, b_x2 = bj.x + bj.z * 0.5f;
                float b_y1 = bj.y - bj.w * 0.5f, b_y2 = bj.y + bj.w * 0.5f;
                float iw = fmaxf(fminf(a_x2, b_x2) - fmaxf(a_x1, b_x1), 0.0f);
                float ih = fmaxf(fminf(a_y2, b_y2) - fmaxf(a_y1, b_y1), 0.0f);
                float inter = iw * ih;
                float uni = bi.z * bi.w + bj.z * bj.w - inter + EPSF;
                float piou = __fdividef(inter, uni);
                if (piou > TAU_C) {
                    float d = fast_sqrt_nn(s);
                    float t = fmaxf(DELTA_C - d, 0.0f);
                    if (t > 0.0f) atomicAdd(&g_acc.accC, t * t);
                }
            }
        }
    } else {
        // ================= loc warps: one box per thread =================
        float accA = 0.0f, accB = 0.0f;
        int i = blockIdx.x * LOC_THREADS + threadIdx.x;
        if (i < N) {
            float4 b1 = pred[i];
            float4 b2 = tgt[i];
            float dv  = dens[i];

            float w1 = b1.z, h1 = b1.w, w2 = b2.z, h2 = b2.w;
            float b1x1 = b1.x - w1 * 0.5f, b1x2 = b1.x + w1 * 0.5f;
            float b1y1 = b1.y - h1 * 0.5f, b1y2 = b1.y + h1 * 0.5f;
            float b2x1 = b2.x - w2 * 0.5f, b2x2 = b2.x + w2 * 0.5f;
            float b2y1 = b2.y - h2 * 0.5f, b2y2 = b2.y + h2 * 0.5f;

            float iw = fmaxf(fminf(b1x2, b2x2) - fmaxf(b1x1, b2x1), 0.0f);
            float ih = fmaxf(fminf(b1y2, b2y2) - fmaxf(b1y1, b2y1), 0.0f);
            float inter = iw * ih;
            float uni   = w1 * h1 + w2 * h2 - inter + EPSF;
            float iou   = __fdividef(inter, uni);

            float cw = fmaxf(b1x2, b2x2) - fminf(b1x1, b2x1);
            float ch = fmaxf(b1y2, b2y2) - fminf(b1y1, b2y1);
            float c2 = cw * cw + ch * ch + EPSF;

            float dx = b2x1 + b2x2 - b1x1 - b1x2;
            float dy = b2y1 + b2y2 - b1y1 - b1y2;
            float rho2 = (dx * dx + dy * dy) * 0.25f;

            // atan(w2/h2) - atan(w1/h1) = atan((w2*h1 - w1*h2)/(h1*h2 + w1*w2))
            float num = w2 * h1 - w1 * h2;
            float den = fmaf(h1, h2, w1 * w2);
            float dat = atanf(__fdividef(num, den));
            float v   = FOUR_PI2 * dat * dat;
            float alpha = __fdividef(v, v - iou + (1.0f + EPSF));
            float ciou = iou - (__fdividef(rho2, c2) + v * alpha);

            float t  = 1.0f - ciou;                   // >= 0
            float pw = t * t * fast_sqrt_nn(t);       // t^2.5
            float dw = fmaf(ALPHA_C, dv, 1.0f);
            float hw = __fdividef(1.0f, 1.0f + __expf(fmaf(5.0f, ciou, -2.5f)));
            accA = dw * hw * pw;
            accB = __fdividef(1.0f, fmaf(w2, h2, 1e-7f));
        }
        #pragma unroll
        for (int off = 16; off > 0; off >>= 1) {
            accA += __shfl_down_sync(0xffffffffu, accA, off);
            accB += __shfl_down_sync(0xffffffffu, accB, off);
        }
        // Fused RED: lane 0 adds accA to &accA, lane 1 adds accB to &accB —
        // ONE RED instruction, two active lanes, spread addresses.
        float bFrom0 = __shfl_sync(0xffffffffu, accB, 0);
        if (lane < 2) {
            float  val  = (lane == 0) ? accA : bFrom0;
            float* addr = (lane == 0) ? &g_acc.accA : &g_acc.accB;
            atomicAdd(addr, val);                     // RED.ADD (no return)
        }
    }

    // ---- block completion: hb edge from all warps, then ONE bump ----
    __syncthreads();
    if (threadIdx.x != 0) return;

    unsigned int prev = atomic_inc_acq_rel(&g_acc.done);
    if (prev != (unsigned int)(nblocks - 1)) return;

    // last block: one v4 load fetches A,B,C from the just-touched sector
    float4 abc = ld_v4(&g_acc);
    out[0] = abc.x * abc.y * invN2 + abc.z * pairScale;
    st_v4(&g_acc, make_float4(0.0f, 0.0f, 0.0f, 0.0f));  // reset for replay
}

extern "C" void kernel_launch(void* const* d_in, const int* in_sizes, int n_in,
                              void* d_out, int out_size) {
    const float4* pred = (const float4*)d_in[0];
    const float4* tgt  = (const float4*)d_in[1];
    const float*  emb  = (const float*)d_in[2];
    const float*  dens = (const float*)d_in[3];
    const int2*   idx  = (const int2*)d_in[4];
    float* out = (float*)d_out;

    int N = in_sizes[0] / 4;
    int D = in_sizes[2] / N;
    int P = in_sizes[4] / 2;

    int blocks = (N + LOC_THREADS - 1) / LOC_THREADS;     // 16
    int pairSlots = blocks * (TPB / 32 - PAIR_WARP0);     // 112
    if (pairSlots < P) blocks = (P + 6) / 7;              // safety (not hit)

    float invN2 = 1.0f / ((float)N * (float)N);
    float pairScale = 0.5f / ((float)P + 1e-7f);

    dosa_split_kernel<<<blocks, TPB>>>(pred, tgt, emb, dens, idx, out,
                                       N, D, P, blocks, invN2, pairScale);
}

// round 13
// speedup vs baseline: 1.1643x; 1.0048x over previous
#include <cuda_runtime.h>
#include <math.h>

// ---------------------------------------------------------------------------
// DOSAConLoss — single-launch, 16-block dedicated-pair-warp version
// (R12 config) + PEELED emb gather: all 4 float4 loads issued before any
// dependent math, removing one serialized L2 round trip from the pair chain
// (the runtime-D loop previously forced load->fma->load->fma).
//
// loss_loc factorizes (reference broadcasts (N,1)/(N,) -> (N,N) mean):
//   loss_loc = (Sum_i dw_i*hw_i*(1-ciou_i)^2.5) * (Sum_j 1/(area_j+1e-7)) / N^2
//
// 16 blocks x 736 threads (23 warps):
//   warps 0-15 : loc, one box per thread (512 boxes/block, 8192 total)
//   warps 16-22: pair, one pair per warp (p = (w-16)*16 + blk, 112 >= 100)
//
// Accumulators {A,B,C,done} in ONE 16B sector. Loc warps: shuffle reduce ->
// ONE RED instruction with lanes 0,1 targeting accA,accB. __syncthreads +
// ONE acq_rel bump per block; last block reads A,B,C with a single v4 load.
// ---------------------------------------------------------------------------

#define EPSF        1e-7f
#define ALPHA_C     1.2f
#define TAU_C       0.3f
#define DELTA_C     1.0f
#define FOUR_PI2    0.40528473456935108577f   // 4/pi^2

#define TPB         736          // 23 warps: 16 loc + 7 pair
#define LOC_THREADS 512
#define PAIR_WARP0  16

struct __align__(16) Acc {
    float accA;            // Σ dw*hw*(1-ciou)^2.5
    float accB;            // Σ 1/(area+1e-7)
    float accC;            // Σ masked pair loss
    unsigned int done;     // block completion counter
};
__device__ Acc g_acc = {0.0f, 0.0f, 0.0f, 0u};

__device__ __forceinline__ unsigned int atomic_inc_acq_rel(unsigned int* p) {
    unsigned int prev;
    asm volatile("atom.acq_rel.gpu.add.u32 %0, [%1], 1;"
                 : "=r"(prev) : "l"(p) : "memory");
    return prev;
}

__device__ __forceinline__ float4 ld_v4(const Acc* p) {
    float4 v;
    asm volatile("ld.global.v4.f32 {%0,%1,%2,%3}, [%4];"
                 : "=f"(v.x), "=f"(v.y), "=f"(v.z), "=f"(v.w)
                 : "l"(p) : "memory");
    return v;
}

__device__ __forceinline__ void st_v4(Acc* p, float4 v) {
    asm volatile("st.global.v4.f32 [%0], {%1,%2,%3,%4};"
                 :: "l"(p), "f"(v.x), "f"(v.y), "f"(v.z), "f"(v.w)
                 : "memory");
}

// fast sqrt for strictly non-negative t (uses MUFU.RSQ)
__device__ __forceinline__ float fast_sqrt_nn(float t) {
    float tc = fmaxf(t, 1e-30f);
    return t * __frsqrt_rn(tc);
}

__global__ __launch_bounds__(TPB)
void dosa_split_kernel(const float4* __restrict__ pred,
                       const float4* __restrict__ tgt,
                       const float*  __restrict__ emb,
                       const float*  __restrict__ dens,
                       const int2*   __restrict__ idx,
                       float* __restrict__ out,
                       int N, int D, int P, int nblocks,
                       float invN2, float pairScale) {
    int lane = threadIdx.x & 31;
    int warp = threadIdx.x >> 5;

    if (warp >= PAIR_WARP0) {
        // ================= dedicated pair warps =================
        // Chain: idx -> (all gathers batched) -> fma -> shuffle -> RED.
        int p = (warp - PAIR_WARP0) * nblocks + blockIdx.x;
        if (p < P) {
            int2 ij = idx[p];
            int pi = ij.x, pj = ij.y;

            const float4* ei = (const float4*)(emb + (size_t)pi * D);
            const float4* ej = (const float4*)(emb + (size_t)pj * D);
            float4 bi = pred[pi];
            float4 bj = pred[pj];

            float s = 0.0f;
            if (D == 256) {
                // PEELED: issue all 4 loads before any dependent math.
                float4 u0 = ei[lane];
                float4 u1 = ei[lane + 32];
                float4 v0 = ej[lane];
                float4 v1 = ej[lane + 32];
                // same accumulation order as the loop (c=lane, then c=lane+32)
                float d0 = u0.x - v0.x, d1 = u0.y - v0.y;
                float d2 = u0.z - v0.z, d3 = u0.w - v0.w;
                s = fmaf(d0, d0, s); s = fmaf(d1, d1, s);
                s = fmaf(d2, d2, s); s = fmaf(d3, d3, s);
                d0 = u1.x - v1.x; d1 = u1.y - v1.y;
                d2 = u1.z - v1.z; d3 = u1.w - v1.w;
                s = fmaf(d0, d0, s); s = fmaf(d1, d1, s);
                s = fmaf(d2, d2, s); s = fmaf(d3, d3, s);
            } else {
                int D4 = D >> 2;
                for (int c = lane; c < D4; c += 32) {
                    float4 u = ei[c];
                    float4 v = ej[c];
                    float d0 = u.x - v.x, d1 = u.y - v.y;
                    float d2 = u.z - v.z, d3 = u.w - v.w;
                    s = fmaf(d0, d0, s); s = fmaf(d1, d1, s);
                    s = fmaf(d2, d2, s); s = fmaf(d3, d3, s);
                }
            }
            #pragma unroll
            for (int off = 16; off > 0; off >>= 1)
                s += __shfl_down_sync(0xffffffffu, s, off);

            if (lane == 0) {
                float a_x1 = bi.x - bi.z * 0.5f, a_x2 = bi.x + bi.z * 0.5f;
                float a_y1 = bi.y - bi.w * 0.5f, a_y2 = bi.y + bi.w * 0.5f;
                float b_x1 = bj.x - bj.z * 0.5f, b_x2 = bj.x + bj.z * 0.5f;
                float b_y1 = bj.y - bj.w * 0.5f, b_y2 = bj.y + bj.w * 0.5f;
                float iw = fmaxf(fminf(a_x2, b_x2) - fmaxf(a_x1, b_x1), 0.0f);
                float ih = fmaxf(fminf(a_y2, b_y2) - fmaxf(a_y1, b_y1), 0.0f);
                float inter = iw * ih;
                float uni = bi.z * bi.w + bj.z * bj.w - inter + EPSF;
                float piou = __fdividef(inter, uni);
                if (piou > TAU_C) {
                    float d = fast_sqrt_nn(s);
                    float t = fmaxf(DELTA_C - d, 0.0f);
                    if (t > 0.0f) atomicAdd(&g_acc.accC, t * t);
                }
            }
        }
    } else {
        // ================= loc warps: one box per thread =================
        float accA = 0.0f, accB = 0.0f;
        int i = blockIdx.x * LOC_THREADS + threadIdx.x;
        if (i < N) {
            float4 b1 = pred[i];
            float4 b2 = tgt[i];
            float dv  = dens[i];

            float w1 = b1.z, h1 = b1.w, w2 = b2.z, h2 = b2.w;
            float b1x1 = b1.x - w1 * 0.5f, b1x2 = b1.x + w1 * 0.5f;
            float b1y1 = b1.y - h1 * 0.5f, b1y2 = b1.y + h1 * 0.5f;
            float b2x1 = b2.x - w2 * 0.5f, b2x2 = b2.x + w2 * 0.5f;
            float b2y1 = b2.y - h2 * 0.5f, b2y2 = b2.y + h2 * 0.5f;

            float iw = fmaxf(fminf(b1x2, b2x2) - fmaxf(b1x1, b2x1), 0.0f);
            float ih = fmaxf(fminf(b1y2, b2y2) - fmaxf(b1y1, b2y1), 0.0f);
            float inter = iw * ih;
            float uni   = w1 * h1 + w2 * h2 - inter + EPSF;
            float iou   = __fdividef(inter, uni);

            float cw = fmaxf(b1x2, b2x2) - fminf(b1x1, b2x1);
            float ch = fmaxf(b1y2, b2y2) - fminf(b1y1, b2y1);
            float c2 = cw * cw + ch * ch + EPSF;

            float dx = b2x1 + b2x2 - b1x1 - b1x2;
            float dy = b2y1 + b2y2 - b1y1 - b1y2;
            float rho2 = (dx * dx + dy * dy) * 0.25f;

            // atan(w2/h2) - atan(w1/h1) = atan((w2*h1 - w1*h2)/(h1*h2 + w1*w2))
            float num = w2 * h1 - w1 * h2;
            float den = fmaf(h1, h2, w1 * w2);
            float dat = atanf(__fdividef(num, den));
            float v   = FOUR_PI2 * dat * dat;
            float alpha = __fdividef(v, v - iou + (1.0f + EPSF));
            float ciou = iou - (__fdividef(rho2, c2) + v * alpha);

            float t  = 1.0f - ciou;                   // >= 0
            float pw = t * t * fast_sqrt_nn(t);       // t^2.5
            float dw = fmaf(ALPHA_C, dv, 1.0f);
            float hw = __fdividef(1.0f, 1.0f + __expf(fmaf(5.0f, ciou, -2.5f)));
            accA = dw * hw * pw;
            accB = __fdividef(1.0f, fmaf(w2, h2, 1e-7f));
        }
        #pragma unroll
        for (int off = 16; off > 0; off >>= 1) {
            accA += __shfl_down_sync(0xffffffffu, accA, off);
            accB += __shfl_down_sync(0xffffffffu, accB, off);
        }
        // Fused RED: lane 0 adds accA to &accA, lane 1 adds accB to &accB —
        // ONE RED instruction, two active lanes, spread addresses.
        float bFrom0 = __shfl_sync(0xffffffffu, accB, 0);
        if (lane < 2) {
            float  val  = (lane == 0) ? accA : bFrom0;
            float* addr = (lane == 0) ? &g_acc.accA : &g_acc.accB;
            atomicAdd(addr, val);                     // RED.ADD (no return)
        }
    }

    // ---- block completion: hb edge from all warps, then ONE bump ----
    __syncthreads();
    if (threadIdx.x != 0) return;

    unsigned int prev = atomic_inc_acq_rel(&g_acc.done);
    if (prev != (unsigned int)(nblocks - 1)) return;

    // last block: one v4 load fetches A,B,C from the just-touched sector
    float4 abc = ld_v4(&g_acc);
    out[0] = abc.x * abc.y * invN2 + abc.z * pairScale;
    st_v4(&g_acc, make_float4(0.0f, 0.0f, 0.0f, 0.0f));  // reset for replay
}

extern "C" void kernel_launch(void* const* d_in, const int* in_sizes, int n_in,
                              void* d_out, int out_size) {
    const float4* pred = (const float4*)d_in[0];
    const float4* tgt  = (const float4*)d_in[1];
    const float*  emb  = (const float*)d_in[2];
    const float*  dens = (const float*)d_in[3];
    const int2*   idx  = (const int2*)d_in[4];
    float* out = (float*)d_out;

    int N = in_sizes[0] / 4;
    int D = in_sizes[2] / N;
    int P = in_sizes[4] / 2;

    int blocks = (N + LOC_THREADS - 1) / LOC_THREADS;     // 16
    int pairSlots = blocks * (TPB / 32 - PAIR_WARP0);     // 112
    if (pairSlots < P) blocks = (P + 6) / 7;              // safety (not hit)

    float invN2 = 1.0f / ((float)N * (float)N);
    float pairScale = 0.5f / ((float)P + 1e-7f);

    dosa_split_kernel<<<blocks, TPB>>>(pred, tgt, emb, dens, idx, out,
                                       N, D, P, blocks, invN2, pairScale);
}